// round 15
// baseline (speedup 1.0000x reference)
#include <cuda_runtime.h>
#include <cuda_bf16.h>
#include <math.h>
#include <stdint.h>

#define NBATCH 4096
#define MDIM   327
#define NDIM   800
#define NLAYERS 9
#define NB     (4096*800)

__device__ float g_PhiTPhi[NDIM*NDIM];
__device__ float g_PhiTb[NB];
__device__ float g_hatx[NB];
__device__ float g_X[2*NB];
__device__ float g_Z[2*NB];
__device__ float g_L[2*NB];
// [conv(2)][tap(9)][var(2)] panels: 32 rows(co) x 64 cols(K) bf16, linear, 4KB each
__device__ __align__(16) unsigned char g_Bpan[2*9*2*4096];

__device__ __forceinline__ uint32_t smem_u32(const void* p){
    uint32_t a; asm("{ .reg .u64 t; cvta.to.shared.u64 t, %1; cvt.u32.u64 %0, t; }":"=r"(a):"l"(p)); return a;
}
__device__ __forceinline__ unsigned pkbf(__nv_bfloat16 a, __nv_bfloat16 b){
    return ((unsigned)__bfloat16_as_ushort(b)<<16)|(unsigned)__bfloat16_as_ushort(a);
}
__device__ __forceinline__ float softf(float v, float s){
    float a = fabsf(v)-s; return a>0.f ? copysignf(a,v) : 0.f;
}

// ---------------- weight panels: var0=[wh|wh] K=64, var1=[wl|0] (K<32 used) ----------------
__global__ void wprep_kernel(const float* __restrict__ c2f, const float* __restrict__ c1b){
    int i = blockIdx.x*blockDim.x + threadIdx.x;
    if (i >= 73728) return;
    int conv = i/36864, r = i%36864;
    int tap = r/4096; r %= 4096;
    int var = r/2048; r %= 2048;
    int row = r/64, col = r%64, ci = col&31;
    const float* src = conv ? c1b : c2f;
    float w = src[row*288 + ci*9 + tap];
    __nv_bfloat16 wh = __float2bfloat16(w), v;
    if (var == 0) v = wh;
    else if (col < 32) v = __float2bfloat16(w - __bfloat162float(wh));
    else v = __float2bfloat16(0.f);
    *(__nv_bfloat16*)(g_Bpan + ((conv*9+tap)*2+var)*4096 + row*128 + col*2) = v;
}

// ---------------- PhiTPhi = W^T W ----------------
__global__ void phitphi_kernel(const float* __restrict__ W){
    __shared__ float sI[32][17], sJ[32][17];
    int tx=threadIdx.x, ty=threadIdx.y, tid=ty*16+tx;
    int i0=blockIdx.y*16, j0=blockIdx.x*16;
    float acc=0.f;
    for (int m0=0; m0<MDIM; m0+=32){
        #pragma unroll
        for (int l=0;l<2;l++){
            int e=tid+l*256, mm=e>>4, c=e&15;
            float vi=0.f, vj=0.f;
            if (m0+mm<MDIM){ vi=W[(m0+mm)*NDIM+i0+c]; vj=W[(m0+mm)*NDIM+j0+c]; }
            sI[mm][c]=vi; sJ[mm][c]=vj;
        }
        __syncthreads();
        #pragma unroll
        for (int mm=0;mm<32;mm++) acc += sI[mm][ty]*sJ[mm][tx];
        __syncthreads();
    }
    g_PhiTPhi[(i0+ty)*NDIM + j0+tx] = acc;
}

// ---------------- Wloss = W W^T - I ----------------
__global__ void wloss_kernel(const float* __restrict__ W, float* __restrict__ out){
    __shared__ float sA[16][33], sB[16][33];
    int tx=threadIdx.x, ty=threadIdx.y, tid=ty*16+tx;
    int i0=blockIdx.y*16, j0=blockIdx.x*16;
    float acc=0.f;
    for (int n0=0;n0<NDIM;n0+=32){
        #pragma unroll
        for (int l=0;l<2;l++){
            int e=tid+l*256, r=e>>5, c=e&31;
            float va=0.f, vb=0.f;
            if (i0+r<MDIM) va=W[(i0+r)*NDIM+n0+c];
            if (j0+r<MDIM) vb=W[(j0+r)*NDIM+n0+c];
            sA[r][c]=va; sB[r][c]=vb;
        }
        __syncthreads();
        #pragma unroll
        for (int c=0;c<32;c++) acc += sA[ty][c]*sB[tx][c];
        __syncthreads();
    }
    int i=i0+ty, j=j0+tx;
    if (i<MDIM && j<MDIM) out[i*MDIM+j] = acc - (i==j?1.f:0.f);
}

// ---------------- fp32 GEMM + fused X-update ----------------
__global__ void gemm_kernel(const float* __restrict__ A, const float* __restrict__ B,
                            float* __restrict__ C, int Mr, int Nc, int Kd, int mode,
                            const float* __restrict__ PTB, const float* __restrict__ HX,
                            const float* __restrict__ Zg, const float* __restrict__ Lg,
                            const float* __restrict__ hArr, const float* __restrict__ b1Arr,
                            int layer, int useZL){
    __shared__ float As[16][68], Bs[16][68];
    int tx=threadIdx.x, ty=threadIdx.y, tid=ty*16+tx;
    int row0=blockIdx.y*64, col0=blockIdx.x*64;
    float acc[4][4];
    #pragma unroll
    for (int i=0;i<4;i++){ acc[i][0]=acc[i][1]=acc[i][2]=acc[i][3]=0.f; }
    for (int k0=0;k0<Kd;k0+=16){
        #pragma unroll
        for (int l=0;l<4;l++){
            int e=tid+l*256, kk=e&15, mm=e>>4;
            float av=0.f;
            int gr=row0+mm, gk=k0+kk;
            if (gr<Mr && gk<Kd) av=A[(size_t)gr*Kd+gk];
            As[kk][mm]=av;
            int nn=e&63, kb=e>>6; float bv=0.f;
            int gc=col0+nn, g2=k0+kb;
            if (gc<Nc && g2<Kd) bv=B[(size_t)g2*Nc+gc];
            Bs[kb][nn]=bv;
        }
        __syncthreads();
        #pragma unroll
        for (int kk=0;kk<16;kk++){
            float4 a=*(const float4*)&As[kk][ty*4];
            float4 b=*(const float4*)&Bs[kk][tx*4];
            float ar[4]={a.x,a.y,a.z,a.w}, br[4]={b.x,b.y,b.z,b.w};
            #pragma unroll
            for (int i=0;i<4;i++)
                #pragma unroll
                for (int j=0;j<4;j++) acc[i][j]+=ar[i]*br[j];
        }
        __syncthreads();
    }
    float hv=0.f, b1=0.f;
    if (mode==1){ hv=hArr[layer]; b1=b1Arr[layer]; }
    #pragma unroll
    for (int i=0;i<4;i++){
        int rr=row0+ty*4+i; if (rr>=Mr) continue;
        #pragma unroll
        for (int j=0;j<4;j++){
            int cc=col0+tx*4+j; if (cc>=Nc) continue;
            size_t idx=(size_t)rr*Nc+cc;
            if (mode==0) C[idx]=acc[i][j];
            else {
                float hx=HX[idx];
                float zt=useZL?Zg[idx]:0.f, lt=useZL?Lg[idx]:0.f;
                C[idx]=hx + hv*(PTB[idx]-acc[i][j]+b1*(zt-hx)-lt);
            }
        }
    }
}

__global__ void xlayer0_kernel(const float* __restrict__ p, float* __restrict__ o,
                               const float* __restrict__ h){
    int i=blockIdx.x*blockDim.x+threadIdx.x;
    if (i<NB) o[i]=h[0]*p[i];
}
__global__ void hatx_kernel(const float* __restrict__ Xc, const float* __restrict__ Xp,
                            float* __restrict__ o, const float* __restrict__ tA,
                            int layer, int up){
    int i=blockIdx.x*blockDim.x+threadIdx.x;
    if (i<NB){ float t=tA[layer]; float v=(1.f+t)*Xc[i]; if (up) v-=t*Xp[i]; o[i]=v; }
}

// ================= mma.sync conv block =================
// A buffer: 992 rows x 128B. Row l = padded pixel (l=43+y*42+x valid, halos zero).
// bf16 mode: [x_hi(32ch)|x_lo(32ch)]; fp32 mode: 32 floats.
// M-tiles: 16 rows; warp w owns tiles (w+8j), j=0..6 -> rows 43+(w+8j)*16 ...
#define AB_OFF  0
#define BB_OFF  126976
#define ZIN_OFF 200704
#define W1_OFF  204400
#define W2_OFF  205552
#define SMEM_TC 206720

__device__ __forceinline__ void stageB(char* Bb, int conv, int tid){
    const uint4* s=(const uint4*)(g_Bpan + conv*73728);
    uint4* d=(uint4*)Bb;
    for (int i=tid;i<4608;i+=256) d[i]=s[i];
}

__device__ __forceinline__ void conv_mma(uint32_t Ab, uint32_t Bb,
                                         float acc[7][4][4], int lane, int wid){
    #pragma unroll
    for (int m=0;m<7;m++)
        #pragma unroll
        for (int n=0;n<4;n++){ acc[m][n][0]=0.f; acc[m][n][1]=0.f; acc[m][n][2]=0.f; acc[m][n][3]=0.f; }
    uint32_t laneA = (uint32_t)(lane&15)*128u + (uint32_t)(lane>>4)*16u;
    uint32_t laneB = (uint32_t)(lane&7)*128u + (uint32_t)((lane>>3)&1)*16u;
    const int OFF[9]={-43,-42,-41,-1,0,1,41,42,43};
    #pragma unroll 1
    for (int tap=0;tap<9;tap++){
        uint32_t Abase = Ab + laneA + (uint32_t)((43+OFF[tap])*128) + (uint32_t)wid*2048u;
        uint32_t Bt = Bb + laneB + (uint32_t)tap*8192u;
        #pragma unroll
        for (int sub=0;sub<6;sub++){
            int var = (sub>=4) ? 1 : 0;
            int k0  = var ? (sub-4)*16 : sub*16;
            uint32_t av = Abase + (uint32_t)(k0*2);
            uint32_t bv = Bt + (uint32_t)var*4096u + (uint32_t)(k0*2);
            uint32_t b[4][2];
            #pragma unroll
            for (int n=0;n<4;n++)
                asm volatile("ldmatrix.sync.aligned.m8n8.x2.shared.b16 {%0,%1}, [%2];"
                    :"=r"(b[n][0]),"=r"(b[n][1]):"r"(bv + (uint32_t)n*1024u));
            #pragma unroll
            for (int m=0;m<7;m++){
                uint32_t a0,a1,a2,a3;
                asm volatile("ldmatrix.sync.aligned.m8n8.x4.shared.b16 {%0,%1,%2,%3}, [%4];"
                    :"=r"(a0),"=r"(a1),"=r"(a2),"=r"(a3):"r"(av + (uint32_t)m*16384u));
                #pragma unroll
                for (int n=0;n<4;n++)
                    asm volatile("mma.sync.aligned.m16n8k16.row.col.f32.bf16.bf16.f32 "
                        "{%0,%1,%2,%3},{%4,%5,%6,%7},{%8,%9},{%0,%1,%2,%3};"
                        :"+f"(acc[m][n][0]),"+f"(acc[m][n][1]),"+f"(acc[m][n][2]),"+f"(acc[m][n][3])
                        :"r"(a0),"r"(a1),"r"(a2),"r"(a3),"r"(b[n][0]),"r"(b[n][1]));
            }
        }
    }
}

// MODE 0: soft->bf16 hi/lo, 1: raw->bf16 hi/lo, 2: relu->fp32
template<int MODE>
__device__ __forceinline__ void wback(char* Ab, float acc[7][4][4],
                                      int lane, int wid, float thr){
    int gid = lane>>2, t2 = (lane&3)*2;
    #pragma unroll
    for (int m=0;m<7;m++){
        int l0 = 43 + (wid + 8*m)*16 + gid;
        #pragma unroll
        for (int hf=0;hf<2;hf++){
            int l = l0 + hf*8;
            int rm = l % 42;
            if (l<=882 && rm>=1 && rm<=40){
                char* row = Ab + (size_t)l*128;
                #pragma unroll
                for (int n=0;n<4;n++){
                    float v0 = acc[m][n][hf*2+0], v1 = acc[m][n][hf*2+1];
                    int ch = n*8 + t2;
                    if (MODE==2){
                        ((float*)row)[ch]   = fmaxf(v0,0.f);
                        ((float*)row)[ch+1] = fmaxf(v1,0.f);
                    } else {
                        if (MODE==0){ v0=softf(v0,thr); v1=softf(v1,thr); }
                        __nv_bfloat16 h0=__float2bfloat16(v0), h1=__float2bfloat16(v1);
                        *(unsigned*)(row + ch*2)      = pkbf(h0,h1);
                        *(unsigned*)(row + 64 + ch*2) = pkbf(__float2bfloat16(v0-__bfloat162float(h0)),
                                                             __float2bfloat16(v1-__bfloat162float(h1)));
                    }
                }
            }
        }
    }
}

__device__ __forceinline__ void pack_row(char* row, const float* f){
    #pragma unroll
    for (int c=0;c<32;c+=2){
        __nv_bfloat16 h0=__float2bfloat16(f[c]), h1=__float2bfloat16(f[c+1]);
        ((unsigned*)row)[c>>1]      = pkbf(h0,h1);
        ((unsigned*)(row+64))[c>>1] = pkbf(__float2bfloat16(f[c]-__bfloat162float(h0)),
                                           __float2bfloat16(f[c+1]-__bfloat162float(h1)));
    }
}

__device__ __forceinline__ float conv2b_px(const char* Ab, const float* w2s, int l){
    const int OFF[9]={-43,-42,-41,-1,0,1,41,42,43};
    float a=0.f;
    #pragma unroll
    for (int t=0;t<9;t++){
        const float* row=(const float*)(Ab+(size_t)(l+OFF[t])*128);
        #pragma unroll
        for (int ci=0;ci<32;ci++) a += w2s[ci*9+t]*row[ci];
    }
    return a;
}

__global__ void __launch_bounds__(256)
conv_tc_kernel(const float* __restrict__ Xn,
               const float* __restrict__ Zc, const float* __restrict__ Zp,
               const float* __restrict__ Lc, const float* __restrict__ Lp,
               float* __restrict__ Znew, float* __restrict__ Lnew,
               float* __restrict__ outZ, float* __restrict__ outSym,
               const float* __restrict__ c1f, const float* __restrict__ c2b,
               const float* __restrict__ hArr, const float* __restrict__ b1Arr,
               const float* __restrict__ b2Arr, const float* __restrict__ tzArr,
               const float* __restrict__ tLArr, const float* __restrict__ thrArr,
               int layer){
    extern __shared__ char sm[];
    char*  Ab  = sm + AB_OFF;
    char*  Bb  = sm + BB_OFF;
    float* zin = (float*)(sm + ZIN_OFF);
    float* w1s = (float*)(sm + W1_OFF);
    float* w2s = (float*)(sm + W2_OFF);
    int tid=threadIdx.x, lane=tid&31, wid=tid>>5, b=blockIdx.x;

    float hv=hArr[layer], b1=b1Arr[layer], b2=b2Arr[layer];
    float tz=tzArr[layer], tL=tLArr[layer], thr=fabsf(thrArr[layer]);
    bool useZc=(layer>=1), useZp=(layer>=2);
    bool useLg=(layer>=2), useLc=(layer>=1), useLp=(layer>=2);

    // init: zero A (992*128B), zin; load small weights; stage conv2f panels
    { uint4 z=make_uint4(0,0,0,0); for (int i=tid;i<7936;i+=256) ((uint4*)Ab)[i]=z; }
    for (int i=tid;i<924;i+=256) zin[i]=0.f;
    for (int i=tid;i<288;i+=256){ w1s[i]=c1f[i]; w2s[i]=c2b[i]; }
    stageB(Bb, 0, tid);
    __syncthreads();          // zeros visible before interior writes (R6 lesson)

    // z_flat -> zin
    for (int p=tid;p<800;p+=256){
        int gi=b*800+p, l=43+(p/40)*42+(p%40);
        float xn=Xn[gi];
        float hz=useZc?(1.f+tz)*Zc[gi]:0.f;
        if (useZp) hz-=tz*Zp[gi];
        float lt=useLg?Lc[gi]:0.f;
        zin[l]=hz+hv*(lt+b2*(xn-hz));
    }
    __syncthreads();

    float acc[7][4][4];
    uint32_t Abu=smem_u32(Ab), Bbu=smem_u32(Bb);
    const int OFF[9]={-43,-42,-41,-1,0,1,41,42,43};

    for (int pass=0; pass<2; pass++){
        // conv1f (1->32) + relu -> Ab bf16 hi/lo
        for (int p=tid;p<800;p+=256){
            int l=43+(p/40)*42+(p%40);
            float v[9];
            #pragma unroll
            for (int t=0;t<9;t++) v[t]=zin[l+OFF[t]];
            float f[32];
            #pragma unroll
            for (int co=0;co<32;co++){
                float s=0.f;
                #pragma unroll
                for (int t=0;t<9;t++) s+=w1s[co*9+t]*v[t];
                f[co]=fmaxf(s,0.f);
            }
            pack_row(Ab+(size_t)l*128, f);
        }
        __syncthreads();

        conv_mma(Abu, Bbu, acc, lane, wid);          // conv2_forward -> x_fwd
        __syncthreads();                             // all reads of Ab done
        if (pass==0) wback<0>(Ab, acc, lane, wid, thr);  // soft(x_fwd)
        else         wback<1>(Ab, acc, lane, wid, 0.f);  // raw x_fwd
        stageB(Bb, 1, tid);                          // conv1b panels
        __syncthreads();

        conv_mma(Abu, Bbu, acc, lane, wid);          // conv1_backward
        __syncthreads();
        wback<2>(Ab, acc, lane, wid, 0.f);           // relu -> fp32 rows
        if (pass==0) stageB(Bb, 0, tid);             // conv2f panels for pass 1
        __syncthreads();

        if (pass==0){
            for (int p=tid;p<800;p+=256){
                int l=43+(p/40)*42+(p%40), gi=b*800+p;
                float zn=conv2b_px(Ab, w2s, l);
                float xn=Xn[gi];
                float hl=useLc?(1.f+tL)*Lc[gi]:0.f;
                if (useLp) hl-=tL*Lp[gi];
                Znew[gi]=zn; outZ[gi]=zn;
                Lnew[gi]=hl+hv*b1*(xn-zn);
            }
        } else {
            for (int p=tid;p<800;p+=256){
                int l=43+(p/40)*42+(p%40);
                float xs=conv2b_px(Ab, w2s, l);
                outSym[b*800+p]=xs-zin[l];
            }
        }
        __syncthreads();                             // epi reads done before pass-1 rewrite
    }
}

// ---------------- launch ----------------
extern "C" void kernel_launch(void* const* d_in, const int* in_sizes, int n_in,
                              void* d_out, int out_size){
    const float* y   = (const float*)d_in[0];
    const float* W   = (const float*)d_in[2];
    const float* b1  = (const float*)d_in[3];
    const float* b2  = (const float*)d_in[4];
    const float* h   = (const float*)d_in[5];
    const float* thr = (const float*)d_in[6];
    const float* txA = (const float*)d_in[7];
    const float* tzA = (const float*)d_in[8];
    const float* tLA = (const float*)d_in[9];
    const float* c1f = (const float*)d_in[10];
    const float* c2f = (const float*)d_in[11];
    const float* c1b = (const float*)d_in[12];
    const float* c2b = (const float*)d_in[13];
    float* out = (float*)d_out;

    cudaFuncSetAttribute(conv_tc_kernel,
                         cudaFuncAttributeMaxDynamicSharedMemorySize, SMEM_TC);

    float *pPTP,*pPTB,*pHX,*pX,*pZ,*pL;
    cudaGetSymbolAddress((void**)&pPTP, g_PhiTPhi);
    cudaGetSymbolAddress((void**)&pPTB, g_PhiTb);
    cudaGetSymbolAddress((void**)&pHX,  g_hatx);
    cudaGetSymbolAddress((void**)&pX,   g_X);
    cudaGetSymbolAddress((void**)&pZ,   g_Z);
    cudaGetSymbolAddress((void**)&pL,   g_L);

    wprep_kernel<<<288, 256>>>(c2f, c1b);
    phitphi_kernel<<<dim3(50,50), dim3(16,16)>>>(W);
    gemm_kernel<<<dim3(13,64), dim3(16,16)>>>(y, W, pPTB, NBATCH, NDIM, MDIM, 0,
                                              nullptr,nullptr,nullptr,nullptr,
                                              nullptr,nullptr, 0, 0);
    wloss_kernel<<<dim3(21,21), dim3(16,16)>>>(W, out + (size_t)2*NLAYERS*NB);

    for (int i=0;i<NLAYERS;i++){
        int cur=i&1, nxt=(i+1)&1;
        if (i==0){
            xlayer0_kernel<<<(NB+255)/256, 256>>>(pPTB, pX+(size_t)nxt*NB, h);
        } else {
            hatx_kernel<<<(NB+255)/256, 256>>>(pX+(size_t)cur*NB, pX+(size_t)nxt*NB,
                                               pHX, txA, i, (i>=2)?1:0);
            gemm_kernel<<<dim3(13,64), dim3(16,16)>>>(pHX, pPTP, pX+(size_t)nxt*NB,
                                                      NBATCH, NDIM, NDIM, 1,
                                                      pPTB, pHX,
                                                      pZ+(size_t)cur*NB, pL+(size_t)cur*NB,
                                                      h, b1, i, (i>=2)?1:0);
        }
        conv_tc_kernel<<<NBATCH, 256, SMEM_TC>>>(
            pX+(size_t)nxt*NB,
            pZ+(size_t)cur*NB, pZ+(size_t)nxt*NB,
            pL+(size_t)cur*NB, pL+(size_t)nxt*NB,
            pZ+(size_t)nxt*NB, pL+(size_t)nxt*NB,
            out+(size_t)i*NB,
            out+(size_t)NLAYERS*NB+(size_t)i*NB,
            c1f, c2b, h, b1, b2, tzA, tLA, thr, i);
    }
}